// round 2
// baseline (speedup 1.0000x reference)
#include <cuda_runtime.h>
#include <cuda_bf16.h>
#include <math.h>

// Problem constants
#define M_PATHS   6
#define N_INST    20000
#define PATH_LEN  4
#define D         128          // D_IN == D_OUT == 128
#define CHUNK     128          // instances per block in score kernel
#define BPM       157          // ceil(20000/128) blocks per path

// Scratch (no allocations allowed -> __device__ globals)
__device__ int   g_stride;                  // 1 if indices are int32, 2 if int64
__device__ float g_u[M_PATHS * D];          // W_enc[m] @ W_att[e,:128]
__device__ float g_v[M_PATHS * D];          // W_enc[m] @ W_att[e,128:]
__device__ float g_c[M_PATHS];              // b_enc[m]·(Wa+Wb) + b_att[e]
__device__ float g_pnum[M_PATHS * BPM * D]; // per-block partial  sum_i e_i * f3_i
__device__ float g_pZ[M_PATHS * BPM];       // per-block partial  sum_i e_i

// ---------------------------------------------------------------------------
// Kernel 0: detect index dtype width. int64 LE with values < 2^31 has every
// odd 32-bit word == 0; int32 node-ids in [0,1e6) make that astronomically
// unlikely across 4 probes.
// ---------------------------------------------------------------------------
__global__ void detect_kernel(const int* __restrict__ inst32) {
    bool is64 = (inst32[1] == 0) && (inst32[3] == 0) &&
                (inst32[5] == 0) && (inst32[7] == 0);
    g_stride = is64 ? 2 : 1;
}

// ---------------------------------------------------------------------------
// Kernel A: fold encoder weights into attention vectors.  6 blocks x 128 thr.
// ---------------------------------------------------------------------------
__global__ void prep_kernel(const float* __restrict__ W_enc,
                            const float* __restrict__ b_enc,
                            const float* __restrict__ W_att,
                            const float* __restrict__ b_att,
                            const int* __restrict__ edge_types32) {
    int m = blockIdx.x;
    int t = threadIdx.x;                 // 0..127
    int e = edge_types32[m * g_stride];  // low word either way (LE)

    __shared__ float sWa[D], sWb[D], red[D];
    sWa[t] = W_att[e * 2 * D + t];
    sWb[t] = W_att[e * 2 * D + D + t];
    __syncthreads();

    const float* W = W_enc + (size_t)m * D * D + (size_t)t * D;  // row d = t
    float u = 0.f, v = 0.f;
    #pragma unroll 8
    for (int h = 0; h < D; h++) {
        float w = W[h];
        u += w * sWa[h];
        v += w * sWb[h];
    }
    g_u[m * D + t] = u;
    g_v[m * D + t] = v;

    red[t] = b_enc[m * D + t] * (sWa[t] + sWb[t]);
    __syncthreads();
    for (int s = 64; s > 0; s >>= 1) {
        if (t < s) red[t] += red[t + s];
        __syncthreads();
    }
    if (t == 0) g_c[m] = red[0] + b_att[e];
}

// ---------------------------------------------------------------------------
// Kernel B: streaming gather + score + exp + weighted-feature accumulation.
// grid = M_PATHS*BPM blocks, 256 threads (8 warps), 1 warp per instance.
// This is the HBM-bound kernel (~123 MB of random 512B row gathers).
// ---------------------------------------------------------------------------
__global__ __launch_bounds__(256) void score_kernel(
        const float* __restrict__ features,
        const int* __restrict__ inst32) {
    int m   = blockIdx.x / BPM;
    int blk = blockIdx.x % BPM;
    int w    = threadIdx.x >> 5;
    int lane = threadIdx.x & 31;
    int st   = g_stride;            // 1 (int32) or 2 (int64, read low word)

    // Each lane owns feature components [4*lane, 4*lane+4)
    const float4 u = ((const float4*)(g_u + m * D))[lane];
    const float4 v = ((const float4*)(g_v + m * D))[lane];
    const float  c = g_c[m];

    const float4* f4 = (const float4*)features;   // row = 32 float4
    float4 accN = make_float4(0.f, 0.f, 0.f, 0.f);
    float  accZ = 0.f;

    int base = blk * CHUNK;
    for (int li = w; li < CHUNK; li += 8) {
        int i = base + li;
        if (i >= N_INST) break;
        size_t off = ((size_t)m * N_INST + i) * PATH_LEN;
        int n0 = inst32[off * st];               // broadcast load
        int n3 = inst32[(off + 3) * st];
        float4 f0 = f4[(size_t)n0 * 32 + lane];
        float4 f3 = f4[(size_t)n3 * 32 + lane];

        float s = f0.x * u.x + f0.y * u.y + f0.z * u.z + f0.w * u.w
                + f3.x * v.x + f3.y * v.y + f3.z * v.z + f3.w * v.w;
        #pragma unroll
        for (int o = 16; o > 0; o >>= 1)
            s += __shfl_xor_sync(0xffffffffu, s, o);
        s += c;
        float lr = s > 0.f ? s : 0.2f * s;     // leaky_relu(0.2)
        float e  = expf(lr);                   // scores are O(1): no max needed

        accZ   += e;
        accN.x += e * f3.x;
        accN.y += e * f3.y;
        accN.z += e * f3.z;
        accN.w += e * f3.w;
    }

    __shared__ float sh_num[8][D];
    __shared__ float sh_Z[8];
    ((float4*)sh_num[w])[lane] = accN;
    if (lane == 0) sh_Z[w] = accZ;
    __syncthreads();

    int t = threadIdx.x;
    if (t < D) {
        float s = 0.f;
        #pragma unroll
        for (int ww = 0; ww < 8; ww++) s += sh_num[ww][t];
        g_pnum[((size_t)(m * BPM + blk)) * D + t] = s;   // write, not add: deterministic
    } else if (t == D) {
        float z = 0.f;
        #pragma unroll
        for (int ww = 0; ww < 8; ww++) z += sh_Z[ww];
        g_pZ[m * BPM + blk] = z;
    }
}

// ---------------------------------------------------------------------------
// Kernel C: reduce partials, tiny GEMVs, path softmax, ELU.  1 block, 128 thr.
// ---------------------------------------------------------------------------
__global__ void finalize_kernel(const float* __restrict__ W_enc,
                                const float* __restrict__ b_enc,
                                const float* __restrict__ w_mp,
                                const float* __restrict__ b_mp,
                                float* __restrict__ out) {
    int t = threadIdx.x;   // 0..127
    __shared__ float sh_g[M_PATHS][D];
    __shared__ float sh_mp[M_PATHS][D];
    __shared__ float red[D];
    __shared__ float sh_Z[M_PATHS];
    __shared__ float sh_ms[M_PATHS];
    __shared__ float sh_mw[M_PATHS];

    // Z_m
    for (int m = 0; m < M_PATHS; m++) {
        float z = 0.f;
        for (int b = t; b < BPM; b += D) z += g_pZ[m * BPM + b];
        red[t] = z; __syncthreads();
        for (int s = 64; s > 0; s >>= 1) {
            if (t < s) red[t] += red[t + s];
            __syncthreads();
        }
        if (t == 0) sh_Z[m] = red[0];
        __syncthreads();
    }

    // g_m = (sum_i e_i f3_i) / Z_m
    for (int m = 0; m < M_PATHS; m++) {
        float n = 0.f;
        for (int b = 0; b < BPM; b++)
            n += g_pnum[((size_t)(m * BPM + b)) * D + t];
        sh_g[m][t] = n / sh_Z[m];
    }
    __syncthreads();

    // mp_out[m] = g_m @ W_enc[m] + b_enc[m]
    for (int m = 0; m < M_PATHS; m++) {
        const float* W = W_enc + (size_t)m * D * D;
        float acc = 0.f;
        #pragma unroll 8
        for (int d = 0; d < D; d++) acc += sh_g[m][d] * W[d * D + t];
        sh_mp[m][t] = acc + b_enc[m * D + t];
    }
    __syncthreads();

    // mp_scores
    for (int m = 0; m < M_PATHS; m++) {
        red[t] = sh_mp[m][t] * w_mp[t];
        __syncthreads();
        for (int s = 64; s > 0; s >>= 1) {
            if (t < s) red[t] += red[t + s];
            __syncthreads();
        }
        if (t == 0) sh_ms[m] = red[0] + b_mp[0];
        __syncthreads();
    }

    // softmax over 6 paths
    if (t == 0) {
        float lr[M_PATHS], mx = -1e30f;
        for (int m = 0; m < M_PATHS; m++) {
            float s = sh_ms[m];
            lr[m] = s > 0.f ? s : 0.2f * s;
            mx = fmaxf(mx, lr[m]);
        }
        float Z = 0.f;
        for (int m = 0; m < M_PATHS; m++) { sh_mw[m] = expf(lr[m] - mx); Z += sh_mw[m]; }
        for (int m = 0; m < M_PATHS; m++) sh_mw[m] /= Z;
    }
    __syncthreads();

    float o = 0.f;
    for (int m = 0; m < M_PATHS; m++) o += sh_mw[m] * sh_mp[m][t];
    out[t] = o > 0.f ? o : expm1f(o);   // elu
}

// ---------------------------------------------------------------------------
extern "C" void kernel_launch(void* const* d_in, const int* in_sizes, int n_in,
                              void* d_out, int out_size) {
    const float* features   = (const float*)d_in[0];
    const float* W_enc      = (const float*)d_in[1];
    const float* b_enc      = (const float*)d_in[2];
    const float* W_att      = (const float*)d_in[3];
    const float* b_att      = (const float*)d_in[4];
    const float* w_mp       = (const float*)d_in[5];
    const float* b_mp       = (const float*)d_in[6];
    const int*   instances  = (const int*)d_in[7];    // int32 or int64 (low words)
    const int*   edge_types = (const int*)d_in[8];

    detect_kernel<<<1, 1>>>(instances);
    prep_kernel<<<M_PATHS, D>>>(W_enc, b_enc, W_att, b_att, edge_types);
    score_kernel<<<M_PATHS * BPM, 256>>>(features, instances);
    finalize_kernel<<<1, D>>>(W_enc, b_enc, w_mp, b_mp, (float*)d_out);
}

// round 5
// speedup vs baseline: 1.9129x; 1.9129x over previous
#include <cuda_runtime.h>
#include <cuda_bf16.h>
#include <math.h>

// Problem constants
#define M_PATHS   6
#define N_INST    20000
#define PATH_LEN  4
#define D         128          // D_IN == D_OUT == 128
#define CHUNK     256          // instances per block in score kernel
#define BPM       79           // ceil(20000/256) blocks per path

// Scratch (no allocations allowed -> __device__ globals)
__device__ int   g_stride;                  // 1 if indices int32, 2 if int64
__device__ float g_u[M_PATHS * D];          // W_enc[m] @ W_att[e,:128]
__device__ float g_v[M_PATHS * D];          // W_enc[m] @ W_att[e,128:]
__device__ float g_c[M_PATHS];              // b_enc·(Wa+Wb) + b_att[e]
__device__ float g_q[M_PATHS * D];          // W_enc[m] @ w_mp
__device__ float g_c2[M_PATHS];             // b_enc·w_mp + b_mp
__device__ float g_pnum[M_PATHS * BPM * D]; // per-block partial sum_i e_i*f3_i
__device__ float g_pZ[M_PATHS * BPM];       // per-block partial sum_i e_i

// ---------------------------------------------------------------------------
// Kernel 0: detect index dtype width (int64 LE < 2^31 -> odd words are 0).
// ---------------------------------------------------------------------------
__global__ void detect_kernel(const int* __restrict__ inst32) {
    bool is64 = (inst32[1] == 0) && (inst32[3] == 0) &&
                (inst32[5] == 0) && (inst32[7] == 0);
    g_stride = is64 ? 2 : 1;
}

// ---------------------------------------------------------------------------
// Kernel A: fold encoder weights into attention vectors + w_mp. 6 x 128.
// ---------------------------------------------------------------------------
__global__ void prep_kernel(const float* __restrict__ W_enc,
                            const float* __restrict__ b_enc,
                            const float* __restrict__ W_att,
                            const float* __restrict__ b_att,
                            const float* __restrict__ w_mp,
                            const float* __restrict__ b_mp,
                            const int* __restrict__ edge_types32) {
    int m = blockIdx.x;
    int t = threadIdx.x;                 // 0..127
    int e = edge_types32[m * g_stride];  // low word either way (LE)

    __shared__ float sWa[D], sWb[D], sWm[D], red[D];
    sWa[t] = W_att[e * 2 * D + t];
    sWb[t] = W_att[e * 2 * D + D + t];
    sWm[t] = w_mp[t];
    __syncthreads();

    const float* W = W_enc + (size_t)m * D * D + (size_t)t * D;  // row d = t
    float u = 0.f, v = 0.f, q = 0.f;
    #pragma unroll 8
    for (int h = 0; h < D; h++) {
        float w = W[h];
        u += w * sWa[h];
        v += w * sWb[h];
        q += w * sWm[h];
    }
    g_u[m * D + t] = u;
    g_v[m * D + t] = v;
    g_q[m * D + t] = q;

    float be = b_enc[m * D + t];
    red[t] = be * (sWa[t] + sWb[t]);
    __syncthreads();
    for (int s = 64; s > 0; s >>= 1) {
        if (t < s) red[t] += red[t + s];
        __syncthreads();
    }
    if (t == 0) g_c[m] = red[0] + b_att[e];
    __syncthreads();

    red[t] = be * sWm[t];
    __syncthreads();
    for (int s = 64; s > 0; s >>= 1) {
        if (t < s) red[t] += red[t + s];
        __syncthreads();
    }
    if (t == 0) g_c2[m] = red[0] + b_mp[0];
}

// ---------------------------------------------------------------------------
// Kernel B: streaming gather + score + exp + weighted-feature accumulation.
// grid = M_PATHS*BPM = 474 blocks, 256 threads, 1 warp per instance.
// HBM-bound: ~123 MB of random 512B row gathers.
// ---------------------------------------------------------------------------
__global__ __launch_bounds__(256) void score_kernel(
        const float* __restrict__ features,
        const int* __restrict__ inst32) {
    int m    = blockIdx.x / BPM;
    int blk  = blockIdx.x % BPM;
    int w    = threadIdx.x >> 5;
    int lane = threadIdx.x & 31;
    int st   = g_stride;            // 1 (int32) or 2 (int64 low word)

    const float4 u = ((const float4*)(g_u + m * D))[lane];
    const float4 v = ((const float4*)(g_v + m * D))[lane];
    const float  c = g_c[m];

    const float4* f4 = (const float4*)features;   // row = 32 float4
    float4 accN = make_float4(0.f, 0.f, 0.f, 0.f);
    float  accZ = 0.f;

    int base = blk * CHUNK;
    for (int li = w; li < CHUNK; li += 8) {
        int i = base + li;
        if (i >= N_INST) break;
        size_t off = ((size_t)m * N_INST + i) * PATH_LEN;
        int n0 = inst32[off * st];               // broadcast load
        int n3 = inst32[(off + 3) * st];
        float4 f0 = f4[(size_t)n0 * 32 + lane];
        float4 f3 = f4[(size_t)n3 * 32 + lane];

        float s = f0.x * u.x + f0.y * u.y + f0.z * u.z + f0.w * u.w
                + f3.x * v.x + f3.y * v.y + f3.z * v.z + f3.w * v.w;
        #pragma unroll
        for (int o = 16; o > 0; o >>= 1)
            s += __shfl_xor_sync(0xffffffffu, s, o);
        s += c;
        float lr = s > 0.f ? s : 0.2f * s;     // leaky_relu(0.2)
        float e  = expf(lr);                   // scores O(1): no max needed

        accZ   += e;
        accN.x += e * f3.x;
        accN.y += e * f3.y;
        accN.z += e * f3.z;
        accN.w += e * f3.w;
    }

    __shared__ float sh_num[8][D];
    __shared__ float sh_Z[8];
    ((float4*)sh_num[w])[lane] = accN;
    if (lane == 0) sh_Z[w] = accZ;
    __syncthreads();

    int t = threadIdx.x;
    if (t < D) {
        float s = 0.f;
        #pragma unroll
        for (int ww = 0; ww < 8; ww++) s += sh_num[ww][t];
        g_pnum[((size_t)(m * BPM + blk)) * D + t] = s;   // write: deterministic
    } else if (t == D) {
        float z = 0.f;
        #pragma unroll
        for (int ww = 0; ww < 8; ww++) z += sh_Z[ww];
        g_pZ[m * BPM + blk] = z;
    }
}

// ---------------------------------------------------------------------------
// Kernel C: fused tail. 1 block x 1024 threads.
//   stage 1: 8-way parallel reduction of per-block partials -> g_m, mp_scores
//   stage 2: path softmax + combined 768-term GEMV + ELU
// out[t] = elu( sum_{m,d} mw_m*g_m[d]*W_enc[m,d,t] + sum_m mw_m*b_enc[m,t] )
// ---------------------------------------------------------------------------
__global__ __launch_bounds__(1024) void finalize_kernel(
        const float* __restrict__ W_enc,
        const float* __restrict__ b_enc,
        float* __restrict__ out) {
    int tid  = threadIdx.x;
    int t    = tid & (D - 1);        // column 0..127
    int part = tid >> 7;             // 0..7

    __shared__ float sh_g[M_PATHS * D];      // g_m[d]
    __shared__ float sh_acc[8][D];
    __shared__ float sh_Z[M_PATHS];
    __shared__ float sh_ms[M_PATHS];
    __shared__ float sh_mw[M_PATHS];

    // --- Z_m: warp 'part<6' handles path 'part' via its first 32 lanes ---
    if (t < 32 && part < M_PATHS) {
        float z = 0.f;
        for (int b = t; b < BPM; b += 32) z += g_pZ[part * BPM + b];
        #pragma unroll
        for (int o = 16; o > 0; o >>= 1)
            z += __shfl_xor_sync(0xffffffffu, z, o);
        if (t == 0) sh_Z[part] = z;
    }

    // --- numerator: each (m,t) column split 8 ways across 'part' ---
    // partials for column t of path m: BPM=79 values; part p takes b = p,p+8,...
    for (int m = 0; m < M_PATHS; m++) {
        const float* p = g_pnum + (size_t)m * BPM * D + t;
        float n = 0.f;
        for (int b = part; b < BPM; b += 8) n += p[(size_t)b * D];
        sh_acc[part][t] = n;
        __syncthreads();
        if (part == 0) {
            float s = 0.f;
            #pragma unroll
            for (int pp = 0; pp < 8; pp++) s += sh_acc[pp][t];
            sh_g[m * D + t] = s / sh_Z[m];
        }
        __syncthreads();
    }

    // --- mp_scores: one warp per path ---
    if (t < 32 && part < M_PATHS) {
        float s = 0.f;
        #pragma unroll
        for (int d = t; d < D; d += 32)
            s += sh_g[part * D + d] * g_q[part * D + d];
        #pragma unroll
        for (int o = 16; o > 0; o >>= 1)
            s += __shfl_xor_sync(0xffffffffu, s, o);
        if (t == 0) sh_ms[part] = s + g_c2[part];
    }
    __syncthreads();

    // --- path softmax ---
    if (tid == 0) {
        float lr[M_PATHS], mx = -1e30f;
        for (int m = 0; m < M_PATHS; m++) {
            float s = sh_ms[m];
            lr[m] = s > 0.f ? s : 0.2f * s;
            mx = fmaxf(mx, lr[m]);
        }
        float Z = 0.f;
        for (int m = 0; m < M_PATHS; m++) { sh_mw[m] = expf(lr[m] - mx); Z += sh_mw[m]; }
        for (int m = 0; m < M_PATHS; m++) sh_mw[m] /= Z;
    }
    __syncthreads();
    if (tid < M_PATHS * D) sh_g[tid] *= sh_mw[tid >> 7];   // h[m,d] = mw_m*g_m[d]
    __syncthreads();

    // --- combined GEMV: 96 of 768 (m,d) terms per part, coalesced W rows ---
    float acc = 0.f;
    int j0 = part * 96;
    #pragma unroll 8
    for (int j = j0; j < j0 + 96; j++)
        acc += sh_g[j] * W_enc[(size_t)j * D + t];
    sh_acc[part][t] = acc;
    __syncthreads();

    if (tid < D) {
        float o = 0.f;
        #pragma unroll
        for (int p = 0; p < 8; p++) o += sh_acc[p][tid];
        #pragma unroll
        for (int m = 0; m < M_PATHS; m++) o += sh_mw[m] * b_enc[m * D + tid];
        out[tid] = o > 0.f ? o : expm1f(o);   // elu
    }
}

// ---------------------------------------------------------------------------
extern "C" void kernel_launch(void* const* d_in, const int* in_sizes, int n_in,
                              void* d_out, int out_size) {
    const float* features   = (const float*)d_in[0];
    const float* W_enc      = (const float*)d_in[1];
    const float* b_enc      = (const float*)d_in[2];
    const float* W_att      = (const float*)d_in[3];
    const float* b_att      = (const float*)d_in[4];
    const float* w_mp       = (const float*)d_in[5];
    const float* b_mp       = (const float*)d_in[6];
    const int*   instances  = (const int*)d_in[7];    // int32 or int64 low words
    const int*   edge_types = (const int*)d_in[8];

    detect_kernel<<<1, 1>>>(instances);
    prep_kernel<<<M_PATHS, D>>>(W_enc, b_enc, W_att, b_att, w_mp, b_mp, edge_types);
    score_kernel<<<M_PATHS * BPM, 256>>>(features, instances);
    finalize_kernel<<<1, 1024>>>(W_enc, b_enc, (float*)d_out);
}